// round 7
// baseline (speedup 1.0000x reference)
#include <cuda_runtime.h>
#include <cstdint>

#define N_NODES 50000
#define E_MAX   850000
#define SCAN_B  1024

// ---------------- scratch (allocation-free: __device__ globals) ----------------
__device__ __align__(128) int   g_cntr[N_NODES];
__device__ __align__(128) int   g_cntc[N_NODES];
__device__ __align__(128) int   g_rp  [N_NODES + 1];
__device__ __align__(128) int   g_fill[N_NODES];
__device__ __align__(128) int   g_bsum[64];
__device__ __align__(128) int   g_boff[64];
__device__ __align__(128) int   g_srt [E_MAX];
__device__ __align__(128) float g_dis [N_NODES];
__device__ __align__(128) float g_h1  [N_NODES * 128];
__device__ __align__(128) float g_AB  [N_NODES * 256];   // [A | B] per node
__device__ __align__(128) float g_Wf  [128 * 256];       // W2 @ [Wc1_top | Wc1_bot]
__device__ __align__(128) float g_bf  [256];             // [b2@Wc1_top + bc1 | b2@Wc1_bot]

// ---------------- helpers ----------------
__device__ __forceinline__ uint32_t f2tf32(float f) {
    uint32_t r; asm("cvt.rna.tf32.f32 %0, %1;" : "=r"(r) : "f"(f)); return r;
}
__device__ __forceinline__ void mma_tf32(float* d, const uint32_t* a, uint32_t b0, uint32_t b1) {
    asm volatile(
        "mma.sync.aligned.m16n8k8.row.col.f32.tf32.tf32.f32 "
        "{%0,%1,%2,%3}, {%4,%5,%6,%7}, {%8,%9}, {%0,%1,%2,%3};"
        : "+f"(d[0]), "+f"(d[1]), "+f"(d[2]), "+f"(d[3])
        : "r"(a[0]), "r"(a[1]), "r"(a[2]), "r"(a[3]), "r"(b0), "r"(b1));
}

// ---------------- CSR build ----------------
__global__ void k_zero(int n) {
    int i = blockIdx.x * blockDim.x + threadIdx.x;
    if (i < n) { g_cntr[i] = 0; g_cntc[i] = 0; }
}
__global__ void k_count(const int* __restrict__ ei, int E) {
    int e = blockIdx.x * blockDim.x + threadIdx.x;
    if (e >= E) return;
    atomicAdd(&g_cntr[__ldg(ei + e)], 1);
    atomicAdd(&g_cntc[__ldg(ei + E + e)], 1);
}
// phase 1: per-block exclusive scan of cntc; also dis = rsqrt(1+cntr)
__global__ __launch_bounds__(SCAN_B) void k_scan_blk(int n) {
    __shared__ int wsum[32];
    int tid = threadIdx.x, lane = tid & 31, wid = tid >> 5;
    int i = blockIdx.x * SCAN_B + tid;
    if (i < n) g_dis[i] = rsqrtf(1.0f + (float)g_cntr[i]);
    int v = (i < n) ? g_cntc[i] : 0;
    int s = v;
#pragma unroll
    for (int o = 1; o < 32; o <<= 1) {
        int t = __shfl_up_sync(0xffffffffu, s, o);
        if (lane >= o) s += t;
    }
    if (lane == 31) wsum[wid] = s;
    __syncthreads();
    if (wid == 0) {
        int ws = wsum[lane];
#pragma unroll
        for (int o = 1; o < 32; o <<= 1) {
            int t = __shfl_up_sync(0xffffffffu, ws, o);
            if (lane >= o) ws += t;
        }
        wsum[lane] = ws;
    }
    __syncthreads();
    int incl = s + (wid ? wsum[wid - 1] : 0);
    if (i < n) g_rp[i] = incl - v;
    if (tid == SCAN_B - 1) g_bsum[blockIdx.x] = incl;
}
// phase 2: exclusive scan of block sums
__global__ void k_scan_top(int nblk, int n) {
    int tid = threadIdx.x;   // 64 threads
    int v = (tid < nblk) ? g_bsum[tid] : 0;
    __shared__ int sh[64];
    sh[tid] = v;
    __syncthreads();
    for (int o = 1; o < 64; o <<= 1) {
        int t = (tid >= o) ? sh[tid - o] : 0;
        __syncthreads();
        sh[tid] += t;
        __syncthreads();
    }
    if (tid < nblk) g_boff[tid] = sh[tid] - v;
    if (tid == nblk - 1) g_rp[n] = sh[tid];
}
// phase 3: add block offsets, copy to fill
__global__ __launch_bounds__(SCAN_B) void k_scan_add(int n) {
    int i = blockIdx.x * SCAN_B + threadIdx.x;
    if (i >= n) return;
    int v = g_rp[i] + g_boff[blockIdx.x];
    g_rp[i] = v;
    g_fill[i] = v;
}
__global__ void k_permute(const int* __restrict__ ei, int E) {
    int e = blockIdx.x * blockDim.x + threadIdx.x;
    if (e >= E) return;
    int r = __ldg(ei + e);
    int c = __ldg(ei + E + e);
    int pos = atomicAdd(&g_fill[c], 1);
    g_srt[pos] = r;
}

// ---------------- fold prep ----------------
__global__ void k_foldw(const float* __restrict__ W2, const float* __restrict__ Wc1) {
    int idx = blockIdx.x * blockDim.x + threadIdx.x;
    if (idx >= 128 * 256) return;
    int k = idx >> 8, n = idx & 255;
    int which = n >> 7, nn = n & 127;
    const float* w2row = W2 + k * 128;
    const float* wc = Wc1 + (which * 128) * 128 + nn;
    float acc = 0.f;
#pragma unroll 8
    for (int j = 0; j < 128; j++) acc = fmaf(__ldg(w2row + j), __ldg(wc + j * 128), acc);
    g_Wf[idx] = acc;
}
__global__ void k_foldbias(const float* __restrict__ b2, const float* __restrict__ Wc1,
                           const float* __restrict__ bc1) {
    int n = threadIdx.x;           // 0..255
    int which = n >> 7, nn = n & 127;
    const float* wc = Wc1 + (which * 128) * 128 + nn;
    float acc = 0.f;
#pragma unroll 8
    for (int j = 0; j < 128; j++) acc = fmaf(b2[j], __ldg(wc + j * 128), acc);
    g_bf[n] = acc + (which ? 0.f : bc1[nn]);
}

// ---------------- conv1: fused gather(x) + GEMM(K=64) + relu -> h1 ----------------
#define SA 68
__global__ __launch_bounds__(256) void k_conv1(
    const float* __restrict__ x, const float* __restrict__ W,
    const float* __restrict__ bias, float* __restrict__ C, int M) {
    extern __shared__ uint32_t sm[];
    uint32_t* As = sm;              // 128*68
    uint32_t* Ws = sm + 128 * SA;   // 128*68
    int tid = threadIdx.x, wid = tid >> 5, lane = tid & 31;
    int row0 = blockIdx.x * 128;
    const float2* x2 = (const float2*)x;

    // gather phase: warp wid -> rows [wid*16, wid*16+16)
    for (int rr = 0; rr < 16; rr++) {
        int r = wid * 16 + rr;
        int node = row0 + r;
        float2 acc = make_float2(0.f, 0.f);
        if (node < M) {
            float di = g_dis[node];
            acc = x2[node * 32 + lane];
            float s2 = di * di;
            acc.x *= s2; acc.y *= s2;
            int e = g_rp[node], end = g_rp[node + 1];
            for (; e + 1 < end; e += 2) {
                int s0 = __ldg(g_srt + e), s1 = __ldg(g_srt + e + 1);
                float n0 = di * __ldg(g_dis + s0);
                float n1 = di * __ldg(g_dis + s1);
                float2 v0 = x2[s0 * 32 + lane];
                float2 v1 = x2[s1 * 32 + lane];
                acc.x += v0.x * n0 + v1.x * n1;
                acc.y += v0.y * n0 + v1.y * n1;
            }
            if (e < end) {
                int s0 = __ldg(g_srt + e);
                float n0 = di * __ldg(g_dis + s0);
                float2 v0 = x2[s0 * 32 + lane];
                acc.x += v0.x * n0; acc.y += v0.y * n0;
            }
        }
        uint2 tv;
        tv.x = f2tf32(acc.x); tv.y = f2tf32(acc.y);
        *(uint2*)(As + r * SA + 2 * lane) = tv;
    }
    // W [64,128] transposed -> Ws[n][k]
    for (int i = tid; i < 64 * 128; i += 256) {
        int k = i >> 7, n = i & 127;
        Ws[n * SA + k] = f2tf32(__ldg(W + k * 128 + n));
    }
    __syncthreads();

    int wm = (wid & 3) * 32, wn = (wid >> 2) * 64;
    int gid = lane >> 2, tig = lane & 3;
    float acc[2][8][4];
#pragma unroll
    for (int ma = 0; ma < 2; ma++)
#pragma unroll
        for (int na = 0; na < 8; na++)
#pragma unroll
            for (int q = 0; q < 4; q++) acc[ma][na][q] = 0.f;

    const uint32_t* a0p = As + (wm + gid) * SA;
    const uint32_t* b0p = Ws + (wn + gid) * SA;
#pragma unroll
    for (int ks = 0; ks < 64; ks += 8) {
        uint32_t afr[2][4];
#pragma unroll
        for (int ma = 0; ma < 2; ma++) {
            const uint32_t* p = a0p + ma * 16 * SA + ks + tig;
            afr[ma][0] = p[0];
            afr[ma][1] = p[8 * SA];
            afr[ma][2] = p[4];
            afr[ma][3] = p[8 * SA + 4];
        }
#pragma unroll
        for (int na = 0; na < 8; na++) {
            const uint32_t* p = b0p + na * 8 * SA + ks + tig;
            uint32_t b0 = p[0], b1 = p[4];
            mma_tf32(acc[0][na], afr[0], b0, b1);
            mma_tf32(acc[1][na], afr[1], b0, b1);
        }
    }

#pragma unroll
    for (int ma = 0; ma < 2; ma++) {
        int r0 = row0 + wm + ma * 16 + gid;
#pragma unroll
        for (int na = 0; na < 8; na++) {
            int c = wn + na * 8 + 2 * tig;
            float bx = bias[c], by = bias[c + 1];
            float2 v0, v1;
            v0.x = fmaxf(acc[ma][na][0] + bx, 0.f); v0.y = fmaxf(acc[ma][na][1] + by, 0.f);
            v1.x = fmaxf(acc[ma][na][2] + bx, 0.f); v1.y = fmaxf(acc[ma][na][3] + by, 0.f);
            if (r0 < M)     *(float2*)(C + (long)r0 * 128 + c)       = v0;
            if (r0 + 8 < M) *(float2*)(C + (long)(r0 + 8) * 128 + c) = v1;
        }
    }
}

// ---------------- conv2: fused gather(h1) + GEMM(K=128, NC=256) -> AB ----------------
#define SAW 132
__global__ __launch_bounds__(512, 1) void k_conv2(float* __restrict__ C, int M) {
    extern __shared__ uint32_t sm[];
    uint32_t* As = sm;                // 128*132
    uint32_t* Ws = sm + 128 * SAW;    // 256*68
    int tid = threadIdx.x, wid = tid >> 5, lane = tid & 31;
    int row0 = blockIdx.x * 128;
    const float4* h4 = (const float4*)g_h1;

    // gather phase: warp wid -> rows [wid*8, wid*8+8)
    for (int rr = 0; rr < 8; rr++) {
        int r = wid * 8 + rr;
        int node = row0 + r;
        float4 acc = make_float4(0.f, 0.f, 0.f, 0.f);
        if (node < M) {
            float di = g_dis[node];
            acc = h4[node * 32 + lane];
            float s2 = di * di;
            acc.x *= s2; acc.y *= s2; acc.z *= s2; acc.w *= s2;
            int e = g_rp[node], end = g_rp[node + 1];
            for (; e + 1 < end; e += 2) {
                int s0 = __ldg(g_srt + e), s1 = __ldg(g_srt + e + 1);
                float n0 = di * __ldg(g_dis + s0);
                float n1 = di * __ldg(g_dis + s1);
                float4 v0 = h4[s0 * 32 + lane];
                float4 v1 = h4[s1 * 32 + lane];
                acc.x += v0.x * n0 + v1.x * n1;
                acc.y += v0.y * n0 + v1.y * n1;
                acc.z += v0.z * n0 + v1.z * n1;
                acc.w += v0.w * n0 + v1.w * n1;
            }
            if (e < end) {
                int s0 = __ldg(g_srt + e);
                float n0 = di * __ldg(g_dis + s0);
                float4 v0 = h4[s0 * 32 + lane];
                acc.x += v0.x * n0; acc.y += v0.y * n0;
                acc.z += v0.z * n0; acc.w += v0.w * n0;
            }
        }
        uint4 tv;
        tv.x = f2tf32(acc.x); tv.y = f2tf32(acc.y);
        tv.z = f2tf32(acc.z); tv.w = f2tf32(acc.w);
        *(uint4*)(As + r * SAW + 4 * lane) = tv;
    }

    int wm = (wid & 3) * 32, wn = (wid >> 2) * 64;   // 16 warps: 4 m-groups x 4 n-groups
    int gid = lane >> 2, tig = lane & 3;
    float acc[2][8][4];
#pragma unroll
    for (int ma = 0; ma < 2; ma++)
#pragma unroll
        for (int na = 0; na < 8; na++)
#pragma unroll
            for (int q = 0; q < 4; q++) acc[ma][na][q] = 0.f;

    for (int kc = 0; kc < 128; kc += 64) {
        // Wf chunk [64 k][256 n] transposed -> Ws[n][k]
        for (int i = tid; i < 64 * 256; i += 512) {
            int k = i >> 8, n = i & 255;
            Ws[n * SA + k] = f2tf32(__ldg(g_Wf + (kc + k) * 256 + n));
        }
        __syncthreads();

        const uint32_t* a0p = As + (wm + gid) * SAW + kc;
        const uint32_t* b0p = Ws + (wn + gid) * SA;
#pragma unroll
        for (int ks = 0; ks < 64; ks += 8) {
            uint32_t afr[2][4];
#pragma unroll
            for (int ma = 0; ma < 2; ma++) {
                const uint32_t* p = a0p + ma * 16 * SAW + ks + tig;
                afr[ma][0] = p[0];
                afr[ma][1] = p[8 * SAW];
                afr[ma][2] = p[4];
                afr[ma][3] = p[8 * SAW + 4];
            }
#pragma unroll
            for (int na = 0; na < 8; na++) {
                const uint32_t* p = b0p + na * 8 * SA + ks + tig;
                uint32_t b0 = p[0], b1 = p[4];
                mma_tf32(acc[0][na], afr[0], b0, b1);
                mma_tf32(acc[1][na], afr[1], b0, b1);
            }
        }
        __syncthreads();
    }

#pragma unroll
    for (int ma = 0; ma < 2; ma++) {
        int r0 = row0 + wm + ma * 16 + gid;
#pragma unroll
        for (int na = 0; na < 8; na++) {
            int c = wn + na * 8 + 2 * tig;
            float bx = g_bf[c], by = g_bf[c + 1];
            float2 v0, v1;
            v0.x = acc[ma][na][0] + bx; v0.y = acc[ma][na][1] + by;
            v1.x = acc[ma][na][2] + bx; v1.y = acc[ma][na][3] + by;
            if (r0 < M)     *(float2*)(C + (long)r0 * 256 + c)       = v0;
            if (r0 + 8 < M) *(float2*)(C + (long)(r0 + 8) * 256 + c) = v1;
        }
    }
}

// ---------------- query ----------------
__global__ void k_query(const int* __restrict__ eli, const float* __restrict__ Wc2,
                        const float* __restrict__ bc2, float* __restrict__ out, int Q) {
    int t = blockIdx.x * blockDim.x + threadIdx.x;
    int q = t >> 5, lane = t & 31;
    if (q >= Q) return;
    int s = __ldg(eli + q);
    int d = __ldg(eli + Q + q);
    float4 a = ((const float4*)g_AB)[s * 64 + lane];
    float4 b = ((const float4*)g_AB)[d * 64 + 32 + lane];
    float4 w = ((const float4*)Wc2)[lane];
    float ux = fmaxf(a.x + b.x, 0.f);
    float uy = fmaxf(a.y + b.y, 0.f);
    float uz = fmaxf(a.z + b.z, 0.f);
    float uw = fmaxf(a.w + b.w, 0.f);
    float sum = ux * w.x + uy * w.y + uz * w.z + uw * w.w;
#pragma unroll
    for (int o = 16; o > 0; o >>= 1) sum += __shfl_xor_sync(0xffffffffu, sum, o);
    if (lane == 0) out[q] = sum + bc2[0];
}

extern "C" void kernel_launch(void* const* d_in, const int* in_sizes, int n_in,
                              void* d_out, int out_size) {
    const float* x   = (const float*)d_in[0];
    const int*   ei  = (const int*)  d_in[1];
    const int*   eli = (const int*)  d_in[2];
    const float* W1  = (const float*)d_in[3];
    const float* b1  = (const float*)d_in[4];
    const float* W2  = (const float*)d_in[5];
    const float* b2  = (const float*)d_in[6];
    const float* Wc1 = (const float*)d_in[7];
    const float* bc1 = (const float*)d_in[8];
    const float* Wc2 = (const float*)d_in[9];
    const float* bc2 = (const float*)d_in[10];
    float* out = (float*)d_out;

    int N = in_sizes[0] / 64;
    int E = in_sizes[1] / 2;
    int Q = in_sizes[2] / 2;

    float *h1, *ABp;
    cudaGetSymbolAddress((void**)&h1,  g_h1);
    cudaGetSymbolAddress((void**)&ABp, g_AB);

    const int SMEM1 = 2 * 128 * SA * 4;            // 69632
    const int SMEM2 = (128 * SAW + 256 * SA) * 4;  // 137216
    cudaFuncSetAttribute(k_conv1, cudaFuncAttributeMaxDynamicSharedMemorySize, SMEM1);
    cudaFuncSetAttribute(k_conv2, cudaFuncAttributeMaxDynamicSharedMemorySize, SMEM2);

    const int B = 256;
    int gblk = (N + 127) / 128;
    int scan_g = (N + SCAN_B - 1) / SCAN_B;

    // CSR build
    k_zero    <<<(N + B - 1) / B, B>>>(N);
    k_count   <<<(E + B - 1) / B, B>>>(ei, E);
    k_scan_blk<<<scan_g, SCAN_B>>>(N);
    k_scan_top<<<1, 64>>>(scan_g, N);
    k_scan_add<<<scan_g, SCAN_B>>>(N);
    k_permute <<<(E + B - 1) / B, B>>>(ei, E);
    // weight fold prep
    k_foldw   <<<(128 * 256 + B - 1) / B, B>>>(W2, Wc1);
    k_foldbias<<<1, 256>>>(b2, Wc1, bc1);
    // fused convs
    k_conv1   <<<gblk, 256, SMEM1>>>(x, W1, b1, h1, N);
    k_conv2   <<<gblk, 512, SMEM2>>>(ABp, N);
    // query
    k_query   <<<((long)Q * 32 + B - 1) / B, B>>>(eli, Wc2, bc2, out, Q);
}

// round 8
// speedup vs baseline: 1.4275x; 1.4275x over previous
#include <cuda_runtime.h>
#include <cstdint>

#define N_NODES 50000
#define E_MAX   850000
#define SCAN_B  1024

// ---------------- scratch (allocation-free: __device__ globals) ----------------
__device__ __align__(128) int   g_cntr[N_NODES];
__device__ __align__(128) int   g_cntc[N_NODES];
__device__ __align__(128) int   g_rp  [N_NODES + 1];
__device__ __align__(128) int   g_fill[N_NODES];
__device__ __align__(128) int   g_bsum[64];
__device__ __align__(128) int   g_srt [E_MAX];
__device__ __align__(128) float g_dis [N_NODES];
__device__ __align__(128) float g_agg1[N_NODES * 64];
__device__ __align__(128) float g_h1  [N_NODES * 128];
__device__ __align__(128) float g_agg2[N_NODES * 128];
__device__ __align__(128) float g_AB  [N_NODES * 256];   // [A | B] per node
__device__ __align__(128) float g_Wf  [128 * 256];       // W2 @ [Wc1_top | Wc1_bot]
__device__ __align__(128) float g_bf  [256];             // [b2@Wc1_top + bc1 | b2@Wc1_bot]

// ---------------- helpers ----------------
__device__ __forceinline__ uint32_t f2tf32(float f) {
    uint32_t r; asm("cvt.rna.tf32.f32 %0, %1;" : "=r"(r) : "f"(f)); return r;
}
__device__ __forceinline__ void mma_tf32(float* d, const uint32_t* a, uint32_t b0, uint32_t b1) {
    asm volatile(
        "mma.sync.aligned.m16n8k8.row.col.f32.tf32.tf32.f32 "
        "{%0,%1,%2,%3}, {%4,%5,%6,%7}, {%8,%9}, {%0,%1,%2,%3};"
        : "+f"(d[0]), "+f"(d[1]), "+f"(d[2]), "+f"(d[3])
        : "r"(a[0]), "r"(a[1]), "r"(a[2]), "r"(a[3]), "r"(b0), "r"(b1));
}

// ---------------- CSR build ----------------
__global__ void k_zero(int n) {
    int i = blockIdx.x * blockDim.x + threadIdx.x;
    if (i < n) { g_cntr[i] = 0; g_cntc[i] = 0; }
}
__global__ void k_count(const int* __restrict__ ei, int E) {
    int e = blockIdx.x * blockDim.x + threadIdx.x;
    if (e >= E) return;
    atomicAdd(&g_cntr[__ldg(ei + e)], 1);
    atomicAdd(&g_cntc[__ldg(ei + E + e)], 1);
}
// phase 1: per-block exclusive scan of cntc; also dis = rsqrt(1+cntr)
__global__ __launch_bounds__(SCAN_B) void k_scan_blk(int n) {
    __shared__ int wsum[32];
    int tid = threadIdx.x, lane = tid & 31, wid = tid >> 5;
    int i = blockIdx.x * SCAN_B + tid;
    if (i < n) g_dis[i] = rsqrtf(1.0f + (float)g_cntr[i]);
    int v = (i < n) ? g_cntc[i] : 0;
    int s = v;
#pragma unroll
    for (int o = 1; o < 32; o <<= 1) {
        int t = __shfl_up_sync(0xffffffffu, s, o);
        if (lane >= o) s += t;
    }
    if (lane == 31) wsum[wid] = s;
    __syncthreads();
    if (wid == 0) {
        int ws = wsum[lane];
#pragma unroll
        for (int o = 1; o < 32; o <<= 1) {
            int t = __shfl_up_sync(0xffffffffu, ws, o);
            if (lane >= o) ws += t;
        }
        wsum[lane] = ws;
    }
    __syncthreads();
    int incl = s + (wid ? wsum[wid - 1] : 0);
    if (i < n) g_rp[i] = incl - v;
    if (tid == SCAN_B - 1) g_bsum[blockIdx.x] = incl;
}
// phase 2+3 merged: each block reduces its own offset from g_bsum, then adds.
__global__ __launch_bounds__(SCAN_B) void k_scan_add(int n, int nblk) {
    __shared__ int red[2];
    int b = blockIdx.x, tid = threadIdx.x;
    if (tid < 64) {
        int v = (tid < b) ? g_bsum[tid] : 0;
#pragma unroll
        for (int o = 16; o > 0; o >>= 1) v += __shfl_down_sync(0xffffffffu, v, o);
        if ((tid & 31) == 0) red[tid >> 5] = v;
    }
    __syncthreads();
    int off = red[0] + red[1];
    int i = b * SCAN_B + tid;
    if (i < n) {
        int v = g_rp[i] + off;
        g_rp[i] = v;
        g_fill[i] = v;
    }
    if (b == nblk - 1 && tid == 0) g_rp[n] = off + g_bsum[b];
}
__global__ void k_permute(const int* __restrict__ ei, int E) {
    int e = blockIdx.x * blockDim.x + threadIdx.x;
    if (e >= E) return;
    int r = __ldg(ei + e);
    int c = __ldg(ei + E + e);
    int pos = atomicAdd(&g_fill[c], 1);
    g_srt[pos] = r;
}

// ---------------- gather convs (warp per node; init term folded in) ----------------
__global__ __launch_bounds__(256) void k_gather1(const float* __restrict__ x, int n) {
    int node = blockIdx.x * 8 + (threadIdx.x >> 5);
    int lane = threadIdx.x & 31;
    if (node >= n) return;
    float di = g_dis[node];
    const float2* x2 = (const float2*)x;
    float2 acc = x2[node * 32 + lane];
    float s2 = di * di;
    acc.x *= s2; acc.y *= s2;
    int e = g_rp[node], end = g_rp[node + 1];
    for (; e + 3 < end; e += 4) {
        int s0 = __ldg(g_srt + e),     s1 = __ldg(g_srt + e + 1);
        int s2i = __ldg(g_srt + e + 2), s3 = __ldg(g_srt + e + 3);
        float n0 = di * __ldg(g_dis + s0);
        float n1 = di * __ldg(g_dis + s1);
        float n2 = di * __ldg(g_dis + s2i);
        float n3 = di * __ldg(g_dis + s3);
        float2 v0 = x2[s0 * 32 + lane];
        float2 v1 = x2[s1 * 32 + lane];
        float2 v2 = x2[s2i * 32 + lane];
        float2 v3 = x2[s3 * 32 + lane];
        acc.x += v0.x * n0 + v1.x * n1 + v2.x * n2 + v3.x * n3;
        acc.y += v0.y * n0 + v1.y * n1 + v2.y * n2 + v3.y * n3;
    }
    for (; e < end; e++) {
        int s0 = __ldg(g_srt + e);
        float n0 = di * __ldg(g_dis + s0);
        float2 v0 = x2[s0 * 32 + lane];
        acc.x += v0.x * n0; acc.y += v0.y * n0;
    }
    ((float2*)g_agg1)[node * 32 + lane] = acc;
}
__global__ __launch_bounds__(256) void k_gather2(int n) {
    int node = blockIdx.x * 8 + (threadIdx.x >> 5);
    int lane = threadIdx.x & 31;
    if (node >= n) return;
    float di = g_dis[node];
    const float4* h4 = (const float4*)g_h1;
    float4 acc = h4[node * 32 + lane];
    float s2 = di * di;
    acc.x *= s2; acc.y *= s2; acc.z *= s2; acc.w *= s2;
    int e = g_rp[node], end = g_rp[node + 1];
    for (; e + 3 < end; e += 4) {
        int s0 = __ldg(g_srt + e),      s1 = __ldg(g_srt + e + 1);
        int s2i = __ldg(g_srt + e + 2), s3 = __ldg(g_srt + e + 3);
        float n0 = di * __ldg(g_dis + s0);
        float n1 = di * __ldg(g_dis + s1);
        float n2 = di * __ldg(g_dis + s2i);
        float n3 = di * __ldg(g_dis + s3);
        float4 v0 = h4[s0 * 32 + lane];
        float4 v1 = h4[s1 * 32 + lane];
        float4 v2 = h4[s2i * 32 + lane];
        float4 v3 = h4[s3 * 32 + lane];
        acc.x += v0.x * n0 + v1.x * n1 + v2.x * n2 + v3.x * n3;
        acc.y += v0.y * n0 + v1.y * n1 + v2.y * n2 + v3.y * n3;
        acc.z += v0.z * n0 + v1.z * n1 + v2.z * n2 + v3.z * n3;
        acc.w += v0.w * n0 + v1.w * n1 + v2.w * n2 + v3.w * n3;
    }
    for (; e < end; e++) {
        int s0 = __ldg(g_srt + e);
        float n0 = di * __ldg(g_dis + s0);
        float4 v0 = h4[s0 * 32 + lane];
        acc.x += v0.x * n0; acc.y += v0.y * n0;
        acc.z += v0.z * n0; acc.w += v0.w * n0;
    }
    ((float4*)g_agg2)[node * 32 + lane] = acc;
}

// ---------------- fold prep (weights + bias in one kernel) ----------------
__global__ void k_foldw(const float* __restrict__ W2, const float* __restrict__ Wc1,
                        const float* __restrict__ b2, const float* __restrict__ bc1) {
    if (blockIdx.x == 128) {
        // bias block: 256 threads
        int n = threadIdx.x;
        int which = n >> 7, nn = n & 127;
        const float* wc = Wc1 + (which * 128) * 128 + nn;
        float acc = 0.f;
#pragma unroll 8
        for (int j = 0; j < 128; j++) acc = fmaf(b2[j], __ldg(wc + j * 128), acc);
        g_bf[n] = acc + (which ? 0.f : bc1[nn]);
        return;
    }
    int idx = blockIdx.x * 256 + threadIdx.x;
    int k = idx >> 8, n = idx & 255;
    int which = n >> 7, nn = n & 127;
    const float* w2row = W2 + k * 128;
    const float* wc = Wc1 + (which * 128) * 128 + nn;
    float acc = 0.f;
#pragma unroll 8
    for (int j = 0; j < 128; j++) acc = fmaf(__ldg(w2row + j), __ldg(wc + j * 128), acc);
    g_Wf[idx] = acc;
}

// ---------------- tf32 mma.sync GEMM ----------------
#define SA 68
template <bool RELU>
__global__ __launch_bounds__(256) void gemm_mma(
    const float* __restrict__ A, const float* __restrict__ W,
    const float* __restrict__ bias, float* __restrict__ C,
    int M, int K, int NC) {
    extern __shared__ uint32_t sm[];
    uint32_t* As = sm;              // 128*68
    uint32_t* Ws = sm + 128 * SA;   // 128*68
    int tid = threadIdx.x, wid = tid >> 5, lane = tid & 31;
    int row0 = blockIdx.x * 128, col0 = blockIdx.y * 128;
    int wm = (wid & 3) * 32, wn = (wid >> 2) * 64;
    int gid = lane >> 2, tig = lane & 3;

    float acc[2][8][4];
#pragma unroll
    for (int ma = 0; ma < 2; ma++)
#pragma unroll
        for (int na = 0; na < 8; na++)
#pragma unroll
            for (int q = 0; q < 4; q++) acc[ma][na][q] = 0.f;

    int lda4 = K >> 2;
    const float4* A4 = (const float4*)A;

    for (int kc = 0; kc < K; kc += 64) {
        for (int i = tid; i < 128 * 16; i += 256) {
            int r = i >> 4, kk = i & 15;
            float4 v = make_float4(0.f, 0.f, 0.f, 0.f);
            int gr = row0 + r;
            if (gr < M) v = A4[gr * lda4 + (kc >> 2) + kk];
            uint4 tv;
            tv.x = f2tf32(v.x); tv.y = f2tf32(v.y); tv.z = f2tf32(v.z); tv.w = f2tf32(v.w);
            *(uint4*)(As + r * SA + kk * 4) = tv;
        }
        for (int i = tid; i < 64 * 128; i += 256) {
            int k = i >> 7, n = i & 127;
            Ws[n * SA + k] = f2tf32(__ldg(W + (kc + k) * NC + col0 + n));
        }
        __syncthreads();

        const uint32_t* a0p = As + (wm + gid) * SA;
        const uint32_t* b0p = Ws + (wn + gid) * SA;
#pragma unroll
        for (int ks = 0; ks < 64; ks += 8) {
            uint32_t afr[2][4];
#pragma unroll
            for (int ma = 0; ma < 2; ma++) {
                const uint32_t* p = a0p + ma * 16 * SA + ks + tig;
                afr[ma][0] = p[0];
                afr[ma][1] = p[8 * SA];
                afr[ma][2] = p[4];
                afr[ma][3] = p[8 * SA + 4];
            }
#pragma unroll
            for (int na = 0; na < 8; na++) {
                const uint32_t* p = b0p + na * 8 * SA + ks + tig;
                uint32_t b0 = p[0], b1 = p[4];
                mma_tf32(acc[0][na], afr[0], b0, b1);
                mma_tf32(acc[1][na], afr[1], b0, b1);
            }
        }
        __syncthreads();
    }

#pragma unroll
    for (int ma = 0; ma < 2; ma++) {
        int r0 = row0 + wm + ma * 16 + gid;
#pragma unroll
        for (int na = 0; na < 8; na++) {
            int c = col0 + wn + na * 8 + 2 * tig;
            float bx = bias[c], by = bias[c + 1];
            float2 v0, v1;
            v0.x = acc[ma][na][0] + bx; v0.y = acc[ma][na][1] + by;
            v1.x = acc[ma][na][2] + bx; v1.y = acc[ma][na][3] + by;
            if (RELU) {
                v0.x = fmaxf(v0.x, 0.f); v0.y = fmaxf(v0.y, 0.f);
                v1.x = fmaxf(v1.x, 0.f); v1.y = fmaxf(v1.y, 0.f);
            }
            if (r0 < M)     *(float2*)(C + (long)r0 * NC + c)       = v0;
            if (r0 + 8 < M) *(float2*)(C + (long)(r0 + 8) * NC + c) = v1;
        }
    }
}

// ---------------- query ----------------
__global__ void k_query(const int* __restrict__ eli, const float* __restrict__ Wc2,
                        const float* __restrict__ bc2, float* __restrict__ out, int Q) {
    int t = blockIdx.x * blockDim.x + threadIdx.x;
    int q = t >> 5, lane = t & 31;
    if (q >= Q) return;
    int s = __ldg(eli + q);
    int d = __ldg(eli + Q + q);
    float4 a = ((const float4*)g_AB)[s * 64 + lane];
    float4 b = ((const float4*)g_AB)[d * 64 + 32 + lane];
    float4 w = ((const float4*)Wc2)[lane];
    float ux = fmaxf(a.x + b.x, 0.f);
    float uy = fmaxf(a.y + b.y, 0.f);
    float uz = fmaxf(a.z + b.z, 0.f);
    float uw = fmaxf(a.w + b.w, 0.f);
    float sum = ux * w.x + uy * w.y + uz * w.z + uw * w.w;
#pragma unroll
    for (int o = 16; o > 0; o >>= 1) sum += __shfl_xor_sync(0xffffffffu, sum, o);
    if (lane == 0) out[q] = sum + bc2[0];
}

extern "C" void kernel_launch(void* const* d_in, const int* in_sizes, int n_in,
                              void* d_out, int out_size) {
    const float* x   = (const float*)d_in[0];
    const int*   ei  = (const int*)  d_in[1];
    const int*   eli = (const int*)  d_in[2];
    const float* W1  = (const float*)d_in[3];
    const float* b1  = (const float*)d_in[4];
    const float* W2  = (const float*)d_in[5];
    const float* b2  = (const float*)d_in[6];
    const float* Wc1 = (const float*)d_in[7];
    const float* bc1 = (const float*)d_in[8];
    const float* Wc2 = (const float*)d_in[9];
    const float* bc2 = (const float*)d_in[10];
    float* out = (float*)d_out;

    int N = in_sizes[0] / 64;
    int E = in_sizes[1] / 2;
    int Q = in_sizes[2] / 2;

    float *agg1, *h1, *ABp, *Wfp, *bfp, *agg2;
    cudaGetSymbolAddress((void**)&agg1, g_agg1);
    cudaGetSymbolAddress((void**)&h1,   g_h1);
    cudaGetSymbolAddress((void**)&ABp,  g_AB);
    cudaGetSymbolAddress((void**)&Wfp,  g_Wf);
    cudaGetSymbolAddress((void**)&bfp,  g_bf);
    cudaGetSymbolAddress((void**)&agg2, g_agg2);

    const int GSMEM = 2 * 128 * SA * 4;   // 69632 B
    cudaFuncSetAttribute(gemm_mma<true>,
                         cudaFuncAttributeMaxDynamicSharedMemorySize, GSMEM);
    cudaFuncSetAttribute(gemm_mma<false>,
                         cudaFuncAttributeMaxDynamicSharedMemorySize, GSMEM);

    const int B = 256;
    int gblk = (N + 127) / 128;
    int nwarp_blk = (N + 7) / 8;
    int scan_g = (N + SCAN_B - 1) / SCAN_B;

    // CSR build
    k_zero    <<<(N + B - 1) / B, B>>>(N);
    k_count   <<<(E + B - 1) / B, B>>>(ei, E);
    k_scan_blk<<<scan_g, SCAN_B>>>(N);
    k_scan_add<<<scan_g, SCAN_B>>>(N, scan_g);
    k_permute <<<(E + B - 1) / B, B>>>(ei, E);
    // weight fold prep (weights + bias in one kernel)
    k_foldw   <<<129, 256>>>(W2, Wc1, b2, bc1);
    // conv1
    k_gather1 <<<nwarp_blk, B>>>(x, N);
    gemm_mma<true> <<<dim3(gblk, 1), 256, GSMEM>>>(agg1, W1, b1, h1, N, 64, 128);
    // conv2 (+ folded classifier layer 1)
    k_gather2 <<<nwarp_blk, B>>>(N);
    gemm_mma<false><<<dim3(gblk, 2), 256, GSMEM>>>(agg2, Wfp, bfp, ABp, N, 128, 256);
    // query
    k_query   <<<((long)Q * 32 + B - 1) / B, B>>>(eli, Wc2, bc2, out, Q);
}

// round 10
// speedup vs baseline: 1.4988x; 1.0499x over previous
#include <cuda_runtime.h>
#include <cstdint>

#define N_NODES 50000
#define E_MAX   850000
#define SCAN_B  1024

// ---------------- scratch (allocation-free: __device__ globals) ----------------
__device__ __align__(128) int   g_cntr[N_NODES];
__device__ __align__(128) int   g_cntc[N_NODES];
__device__ __align__(128) int   g_rp  [N_NODES + 1];
__device__ __align__(128) int   g_fill[N_NODES];
__device__ __align__(128) int   g_bsum[64];
__device__ __align__(128) int   g_srt [E_MAX];
__device__ __align__(128) float g_dis [N_NODES];
__device__ __align__(128) float g_agg1[N_NODES * 64];
__device__ __align__(128) float g_h1  [N_NODES * 128];
__device__ __align__(128) float g_agg2[N_NODES * 128];
__device__ __align__(128) float g_AB  [N_NODES * 256];   // [A | B] per node
__device__ __align__(128) float g_Wf  [128 * 256];       // W2 @ [Wc1_top | Wc1_bot]
__device__ __align__(128) float g_bf  [256];             // [b2@Wc1_top + bc1 | b2@Wc1_bot]

// ---------------- helpers ----------------
__device__ __forceinline__ uint32_t f2tf32(float f) {
    uint32_t r; asm("cvt.rna.tf32.f32 %0, %1;" : "=r"(r) : "f"(f)); return r;
}
__device__ __forceinline__ void mma_tf32(float* d, const uint32_t* a, uint32_t b0, uint32_t b1) {
    asm volatile(
        "mma.sync.aligned.m16n8k8.row.col.f32.tf32.tf32.f32 "
        "{%0,%1,%2,%3}, {%4,%5,%6,%7}, {%8,%9}, {%0,%1,%2,%3};"
        : "+f"(d[0]), "+f"(d[1]), "+f"(d[2]), "+f"(d[3])
        : "r"(a[0]), "r"(a[1]), "r"(a[2]), "r"(a[3]), "r"(b0), "r"(b1));
}

// ---------------- CSR build ----------------
__global__ void k_zero(int n) {
    int i = blockIdx.x * blockDim.x + threadIdx.x;
    if (i < n) { g_cntr[i] = 0; g_cntc[i] = 0; }
}
__global__ void k_count(const int* __restrict__ ei, int E) {
    int e = blockIdx.x * blockDim.x + threadIdx.x;
    if (e >= E) return;
    atomicAdd(&g_cntr[__ldg(ei + e)], 1);
    atomicAdd(&g_cntc[__ldg(ei + E + e)], 1);
}
// phase 1: per-block exclusive scan of cntc; also dis = rsqrt(1+cntr)
__global__ __launch_bounds__(SCAN_B) void k_scan_blk(int n) {
    __shared__ int wsum[32];
    int tid = threadIdx.x, lane = tid & 31, wid = tid >> 5;
    int i = blockIdx.x * SCAN_B + tid;
    if (i < n) g_dis[i] = rsqrtf(1.0f + (float)g_cntr[i]);
    int v = (i < n) ? g_cntc[i] : 0;
    int s = v;
#pragma unroll
    for (int o = 1; o < 32; o <<= 1) {
        int t = __shfl_up_sync(0xffffffffu, s, o);
        if (lane >= o) s += t;
    }
    if (lane == 31) wsum[wid] = s;
    __syncthreads();
    if (wid == 0) {
        int ws = wsum[lane];
#pragma unroll
        for (int o = 1; o < 32; o <<= 1) {
            int t = __shfl_up_sync(0xffffffffu, ws, o);
            if (lane >= o) ws += t;
        }
        wsum[lane] = ws;
    }
    __syncthreads();
    int incl = s + (wid ? wsum[wid - 1] : 0);
    if (i < n) g_rp[i] = incl - v;
    if (tid == SCAN_B - 1) g_bsum[blockIdx.x] = incl;
}
// phase 2+3 merged: each block reduces its own offset from g_bsum, then adds.
__global__ __launch_bounds__(SCAN_B) void k_scan_add(int n, int nblk) {
    __shared__ int red[2];
    int b = blockIdx.x, tid = threadIdx.x;
    if (tid < 64) {
        int v = (tid < b) ? g_bsum[tid] : 0;
#pragma unroll
        for (int o = 16; o > 0; o >>= 1) v += __shfl_down_sync(0xffffffffu, v, o);
        if ((tid & 31) == 0) red[tid >> 5] = v;
    }
    __syncthreads();
    int off = red[0] + red[1];
    int i = b * SCAN_B + tid;
    if (i < n) {
        int v = g_rp[i] + off;
        g_rp[i] = v;
        g_fill[i] = v;
    }
    if (b == nblk - 1 && tid == 0) g_rp[n] = off + g_bsum[b];
}
__global__ void k_permute(const int* __restrict__ ei, int E) {
    int e = blockIdx.x * blockDim.x + threadIdx.x;
    if (e >= E) return;
    int r = __ldg(ei + e);
    int c = __ldg(ei + E + e);
    int pos = atomicAdd(&g_fill[c], 1);
    g_srt[pos] = r;
}

// ---------------- gather convs (warp per node; init term folded in; R6 bodies) ----------------
__global__ __launch_bounds__(256) void k_gather1(const float* __restrict__ x, int n) {
    int node = blockIdx.x * 8 + (threadIdx.x >> 5);
    int lane = threadIdx.x & 31;
    if (node >= n) return;
    float di = g_dis[node];
    const float2* x2 = (const float2*)x;
    float2 acc = x2[node * 32 + lane];
    float s2 = di * di;
    acc.x *= s2; acc.y *= s2;
    int e = g_rp[node], end = g_rp[node + 1];
    for (; e + 1 < end; e += 2) {
        int s0 = __ldg(g_srt + e), s1 = __ldg(g_srt + e + 1);
        float n0 = di * __ldg(g_dis + s0);
        float n1 = di * __ldg(g_dis + s1);
        float2 v0 = x2[s0 * 32 + lane];
        float2 v1 = x2[s1 * 32 + lane];
        acc.x += v0.x * n0 + v1.x * n1;
        acc.y += v0.y * n0 + v1.y * n1;
    }
    if (e < end) {
        int s0 = __ldg(g_srt + e);
        float n0 = di * __ldg(g_dis + s0);
        float2 v0 = x2[s0 * 32 + lane];
        acc.x += v0.x * n0; acc.y += v0.y * n0;
    }
    ((float2*)g_agg1)[node * 32 + lane] = acc;
}
__global__ __launch_bounds__(256) void k_gather2(int n) {
    int node = blockIdx.x * 8 + (threadIdx.x >> 5);
    int lane = threadIdx.x & 31;
    if (node >= n) return;
    float di = g_dis[node];
    const float4* h4 = (const float4*)g_h1;
    float4 acc = h4[node * 32 + lane];
    float s2 = di * di;
    acc.x *= s2; acc.y *= s2; acc.z *= s2; acc.w *= s2;
    int e = g_rp[node], end = g_rp[node + 1];
    for (; e + 1 < end; e += 2) {
        int s0 = __ldg(g_srt + e), s1 = __ldg(g_srt + e + 1);
        float n0 = di * __ldg(g_dis + s0);
        float n1 = di * __ldg(g_dis + s1);
        float4 v0 = h4[s0 * 32 + lane];
        float4 v1 = h4[s1 * 32 + lane];
        acc.x += v0.x * n0 + v1.x * n1;
        acc.y += v0.y * n0 + v1.y * n1;
        acc.z += v0.z * n0 + v1.z * n1;
        acc.w += v0.w * n0 + v1.w * n1;
    }
    if (e < end) {
        int s0 = __ldg(g_srt + e);
        float n0 = di * __ldg(g_dis + s0);
        float4 v0 = h4[s0 * 32 + lane];
        acc.x += v0.x * n0; acc.y += v0.y * n0;
        acc.z += v0.z * n0; acc.w += v0.w * n0;
    }
    ((float4*)g_agg2)[node * 32 + lane] = acc;
}

// ---------------- fold prep (weights + bias in one kernel) ----------------
__global__ void k_foldw(const float* __restrict__ W2, const float* __restrict__ Wc1,
                        const float* __restrict__ b2, const float* __restrict__ bc1) {
    if (blockIdx.x == 128) {
        int n = threadIdx.x;
        int which = n >> 7, nn = n & 127;
        const float* wc = Wc1 + (which * 128) * 128 + nn;
        float acc = 0.f;
#pragma unroll 8
        for (int j = 0; j < 128; j++) acc = fmaf(b2[j], __ldg(wc + j * 128), acc);
        g_bf[n] = acc + (which ? 0.f : bc1[nn]);
        return;
    }
    int idx = blockIdx.x * 256 + threadIdx.x;
    int k = idx >> 8, n = idx & 255;
    int which = n >> 7, nn = n & 127;
    const float* w2row = W2 + k * 128;
    const float* wc = Wc1 + (which * 128) * 128 + nn;
    float acc = 0.f;
#pragma unroll 8
    for (int j = 0; j < 128; j++) acc = fmaf(__ldg(w2row + j), __ldg(wc + j * 128), acc);
    g_Wf[idx] = acc;
}

// ---------------- tf32 mma.sync GEMM ----------------
#define SA 68
template <bool RELU>
__global__ __launch_bounds__(256) void gemm_mma(
    const float* __restrict__ A, const float* __restrict__ W,
    const float* __restrict__ bias, float* __restrict__ C,
    int M, int K, int NC) {
    extern __shared__ uint32_t sm[];
    uint32_t* As = sm;              // 128*68
    uint32_t* Ws = sm + 128 * SA;   // 128*68
    int tid = threadIdx.x, wid = tid >> 5, lane = tid & 31;
    int row0 = blockIdx.x * 128, col0 = blockIdx.y * 128;
    int wm = (wid & 3) * 32, wn = (wid >> 2) * 64;
    int gid = lane >> 2, tig = lane & 3;

    float acc[2][8][4];
#pragma unroll
    for (int ma = 0; ma < 2; ma++)
#pragma unroll
        for (int na = 0; na < 8; na++)
#pragma unroll
            for (int q = 0; q < 4; q++) acc[ma][na][q] = 0.f;

    int lda4 = K >> 2;
    const float4* A4 = (const float4*)A;

    for (int kc = 0; kc < K; kc += 64) {
        for (int i = tid; i < 128 * 16; i += 256) {
            int r = i >> 4, kk = i & 15;
            float4 v = make_float4(0.f, 0.f, 0.f, 0.f);
            int gr = row0 + r;
            if (gr < M) v = A4[gr * lda4 + (kc >> 2) + kk];
            uint4 tv;
            tv.x = f2tf32(v.x); tv.y = f2tf32(v.y); tv.z = f2tf32(v.z); tv.w = f2tf32(v.w);
            *(uint4*)(As + r * SA + kk * 4) = tv;
        }
        for (int i = tid; i < 64 * 128; i += 256) {
            int k = i >> 7, n = i & 127;
            Ws[n * SA + k] = f2tf32(__ldg(W + (kc + k) * NC + col0 + n));
        }
        __syncthreads();

        const uint32_t* a0p = As + (wm + gid) * SA;
        const uint32_t* b0p = Ws + (wn + gid) * SA;
#pragma unroll
        for (int ks = 0; ks < 64; ks += 8) {
            uint32_t afr[2][4];
#pragma unroll
            for (int ma = 0; ma < 2; ma++) {
                const uint32_t* p = a0p + ma * 16 * SA + ks + tig;
                afr[ma][0] = p[0];
                afr[ma][1] = p[8 * SA];
                afr[ma][2] = p[4];
                afr[ma][3] = p[8 * SA + 4];
            }
#pragma unroll
            for (int na = 0; na < 8; na++) {
                const uint32_t* p = b0p + na * 8 * SA + ks + tig;
                uint32_t b0 = p[0], b1 = p[4];
                mma_tf32(acc[0][na], afr[0], b0, b1);
                mma_tf32(acc[1][na], afr[1], b0, b1);
            }
        }
        __syncthreads();
    }

#pragma unroll
    for (int ma = 0; ma < 2; ma++) {
        int r0 = row0 + wm + ma * 16 + gid;
#pragma unroll
        for (int na = 0; na < 8; na++) {
            int c = col0 + wn + na * 8 + 2 * tig;
            float bx = bias[c], by = bias[c + 1];
            float2 v0, v1;
            v0.x = acc[ma][na][0] + bx; v0.y = acc[ma][na][1] + by;
            v1.x = acc[ma][na][2] + bx; v1.y = acc[ma][na][3] + by;
            if (RELU) {
                v0.x = fmaxf(v0.x, 0.f); v0.y = fmaxf(v0.y, 0.f);
                v1.x = fmaxf(v1.x, 0.f); v1.y = fmaxf(v1.y, 0.f);
            }
            if (r0 < M)     *(float2*)(C + (long)r0 * NC + c)       = v0;
            if (r0 + 8 < M) *(float2*)(C + (long)(r0 + 8) * NC + c) = v1;
        }
    }
}

// ---------------- query ----------------
__global__ void k_query(const int* __restrict__ eli, const float* __restrict__ Wc2,
                        const float* __restrict__ bc2, float* __restrict__ out, int Q) {
    int t = blockIdx.x * blockDim.x + threadIdx.x;
    int q = t >> 5, lane = t & 31;
    if (q >= Q) return;
    int s = __ldg(eli + q);
    int d = __ldg(eli + Q + q);
    float4 a = ((const float4*)g_AB)[s * 64 + lane];
    float4 b = ((const float4*)g_AB)[d * 64 + 32 + lane];
    float4 w = ((const float4*)Wc2)[lane];
    float ux = fmaxf(a.x + b.x, 0.f);
    float uy = fmaxf(a.y + b.y, 0.f);
    float uz = fmaxf(a.z + b.z, 0.f);
    float uw = fmaxf(a.w + b.w, 0.f);
    float sum = ux * w.x + uy * w.y + uz * w.z + uw * w.w;
#pragma unroll
    for (int o = 16; o > 0; o >>= 1) sum += __shfl_xor_sync(0xffffffffu, sum, o);
    if (lane == 0) out[q] = sum + bc2[0];
}

extern "C" void kernel_launch(void* const* d_in, const int* in_sizes, int n_in,
                              void* d_out, int out_size) {
    const float* x   = (const float*)d_in[0];
    const int*   ei  = (const int*)  d_in[1];
    const int*   eli = (const int*)  d_in[2];
    const float* W1  = (const float*)d_in[3];
    const float* b1  = (const float*)d_in[4];
    const float* W2  = (const float*)d_in[5];
    const float* b2  = (const float*)d_in[6];
    const float* Wc1 = (const float*)d_in[7];
    const float* bc1 = (const float*)d_in[8];
    const float* Wc2 = (const float*)d_in[9];
    const float* bc2 = (const float*)d_in[10];
    float* out = (float*)d_out;

    int N = in_sizes[0] / 64;
    int E = in_sizes[1] / 2;
    int Q = in_sizes[2] / 2;

    float *agg1, *h1, *ABp, *Wfp, *bfp, *agg2;
    cudaGetSymbolAddress((void**)&agg1, g_agg1);
    cudaGetSymbolAddress((void**)&h1,   g_h1);
    cudaGetSymbolAddress((void**)&ABp,  g_AB);
    cudaGetSymbolAddress((void**)&Wfp,  g_Wf);
    cudaGetSymbolAddress((void**)&bfp,  g_bf);
    cudaGetSymbolAddress((void**)&agg2, g_agg2);

    const int GSMEM = 2 * 128 * SA * 4;   // 69632 B
    cudaFuncSetAttribute(gemm_mma<true>,
                         cudaFuncAttributeMaxDynamicSharedMemorySize, GSMEM);
    cudaFuncSetAttribute(gemm_mma<false>,
                         cudaFuncAttributeMaxDynamicSharedMemorySize, GSMEM);

    const int B = 256;
    int gblk = (N + 127) / 128;
    int nwarp_blk = (N + 7) / 8;
    int scan_g = (N + SCAN_B - 1) / SCAN_B;

    // CSR build
    k_zero    <<<(N + B - 1) / B, B>>>(N);
    k_count   <<<(E + B - 1) / B, B>>>(ei, E);
    k_scan_blk<<<scan_g, SCAN_B>>>(N);
    k_scan_add<<<scan_g, SCAN_B>>>(N, scan_g);
    k_permute <<<(E + B - 1) / B, B>>>(ei, E);
    // weight fold prep (weights + bias in one kernel)
    k_foldw   <<<129, 256>>>(W2, Wc1, b2, bc1);
    // conv1
    k_gather1 <<<nwarp_blk, B>>>(x, N);
    gemm_mma<true> <<<dim3(gblk, 1), 256, GSMEM>>>(agg1, W1, b1, h1, N, 64, 128);
    // conv2 (+ folded classifier layer 1)
    k_gather2 <<<nwarp_blk, B>>>(N);
    gemm_mma<false><<<dim3(gblk, 2), 256, GSMEM>>>(agg2, Wfp, bfp, ABp, N, 128, 256);
    // query
    k_query   <<<((long)Q * 32 + B - 1) / B, B>>>(eli, Wc2, bc2, out, Q);
}

// round 11
// speedup vs baseline: 1.5105x; 1.0078x over previous
#include <cuda_runtime.h>
#include <cuda_fp16.h>
#include <cstdint>

#define N_NODES 50000
#define E_MAX   850000
#define SCAN_B  1024

// ---------------- scratch (allocation-free: __device__ globals) ----------------
__device__ __align__(128) int    g_cntr[N_NODES];
__device__ __align__(128) int    g_cntc[N_NODES];
__device__ __align__(128) int    g_rp  [N_NODES + 1];
__device__ __align__(128) int    g_fill[N_NODES];
__device__ __align__(128) int    g_bsum[64];
__device__ __align__(128) int    g_srt [E_MAX];
__device__ __align__(128) float  g_dis [N_NODES];
__device__ __align__(128) __half g_xh  [N_NODES * 64];    // fp16 copy of x
__device__ __align__(128) float  g_agg1[N_NODES * 64];
__device__ __align__(128) __half g_h1h [N_NODES * 128];   // fp16 h1
__device__ __align__(128) float  g_agg2[N_NODES * 128];
__device__ __align__(128) float  g_AB  [N_NODES * 256];   // [A | B] per node
__device__ __align__(128) float  g_Wf  [128 * 256];       // W2 @ [Wc1_top | Wc1_bot]
__device__ __align__(128) float  g_bf  [256];             // [b2@Wc1_top + bc1 | b2@Wc1_bot]

// ---------------- helpers ----------------
__device__ __forceinline__ uint32_t f2tf32(float f) {
    uint32_t r; asm("cvt.rna.tf32.f32 %0, %1;" : "=r"(r) : "f"(f)); return r;
}
__device__ __forceinline__ void mma_tf32(float* d, const uint32_t* a, uint32_t b0, uint32_t b1) {
    asm volatile(
        "mma.sync.aligned.m16n8k8.row.col.f32.tf32.tf32.f32 "
        "{%0,%1,%2,%3}, {%4,%5,%6,%7}, {%8,%9}, {%0,%1,%2,%3};"
        : "+f"(d[0]), "+f"(d[1]), "+f"(d[2]), "+f"(d[3])
        : "r"(a[0]), "r"(a[1]), "r"(a[2]), "r"(a[3]), "r"(b0), "r"(b1));
}

// ---------------- CSR build ----------------
__global__ void k_zero(int n) {
    int i = blockIdx.x * blockDim.x + threadIdx.x;
    if (i < n) { g_cntr[i] = 0; g_cntc[i] = 0; }
}
__global__ void k_count(const int* __restrict__ ei, int E) {
    int e = blockIdx.x * blockDim.x + threadIdx.x;
    if (e >= E) return;
    atomicAdd(&g_cntr[__ldg(ei + e)], 1);
    atomicAdd(&g_cntc[__ldg(ei + E + e)], 1);
}
// phase 1: per-block exclusive scan of cntc; also dis = rsqrt(1+cntr)
__global__ __launch_bounds__(SCAN_B) void k_scan_blk(int n) {
    __shared__ int wsum[32];
    int tid = threadIdx.x, lane = tid & 31, wid = tid >> 5;
    int i = blockIdx.x * SCAN_B + tid;
    if (i < n) g_dis[i] = rsqrtf(1.0f + (float)g_cntr[i]);
    int v = (i < n) ? g_cntc[i] : 0;
    int s = v;
#pragma unroll
    for (int o = 1; o < 32; o <<= 1) {
        int t = __shfl_up_sync(0xffffffffu, s, o);
        if (lane >= o) s += t;
    }
    if (lane == 31) wsum[wid] = s;
    __syncthreads();
    if (wid == 0) {
        int ws = wsum[lane];
#pragma unroll
        for (int o = 1; o < 32; o <<= 1) {
            int t = __shfl_up_sync(0xffffffffu, ws, o);
            if (lane >= o) ws += t;
        }
        wsum[lane] = ws;
    }
    __syncthreads();
    int incl = s + (wid ? wsum[wid - 1] : 0);
    if (i < n) g_rp[i] = incl - v;
    if (tid == SCAN_B - 1) g_bsum[blockIdx.x] = incl;
}
// phase 2+3 merged: each block reduces its own offset from g_bsum, then adds.
__global__ __launch_bounds__(SCAN_B) void k_scan_add(int n, int nblk) {
    __shared__ int red[2];
    int b = blockIdx.x, tid = threadIdx.x;
    if (tid < 64) {
        int v = (tid < b) ? g_bsum[tid] : 0;
#pragma unroll
        for (int o = 16; o > 0; o >>= 1) v += __shfl_down_sync(0xffffffffu, v, o);
        if ((tid & 31) == 0) red[tid >> 5] = v;
    }
    __syncthreads();
    int off = red[0] + red[1];
    int i = b * SCAN_B + tid;
    if (i < n) {
        int v = g_rp[i] + off;
        g_rp[i] = v;
        g_fill[i] = v;
    }
    if (b == nblk - 1 && tid == 0) g_rp[n] = off + g_bsum[b];
}
__global__ void k_permute(const int* __restrict__ ei, int E) {
    int e = blockIdx.x * blockDim.x + threadIdx.x;
    if (e >= E) return;
    int r = __ldg(ei + e);
    int c = __ldg(ei + E + e);
    int pos = atomicAdd(&g_fill[c], 1);
    g_srt[pos] = r;
}

// ---------------- x -> fp16 convert ----------------
__global__ void k_xcvt(const float* __restrict__ x, int n16) {   // n16 = N*16 float4s
    int i = blockIdx.x * blockDim.x + threadIdx.x;
    if (i >= n16) return;
    float4 v = ((const float4*)x)[i];
    __half2 a = __floats2half2_rn(v.x, v.y);
    __half2 b = __floats2half2_rn(v.z, v.w);
    uint2 u;
    u.x = *(uint32_t*)&a;
    u.y = *(uint32_t*)&b;
    ((uint2*)g_xh)[i] = u;
}

// ---------------- gather convs (warp per node; init term folded in) ----------------
// agg1[i] = xh[i]*dis^2 + sum_e xh[src]*nrm     (64 halves/row = 32 half2; lane -> 1 half2)
__global__ __launch_bounds__(256) void k_gather1(int n) {
    int node = blockIdx.x * 8 + (threadIdx.x >> 5);
    int lane = threadIdx.x & 31;
    if (node >= n) return;
    float di = g_dis[node];
    const __half2* xh2 = (const __half2*)g_xh;
    float2 acc = __half22float2(xh2[node * 32 + lane]);
    float s2 = di * di;
    acc.x *= s2; acc.y *= s2;
    int e = g_rp[node], end = g_rp[node + 1];
    for (; e + 1 < end; e += 2) {
        int s0 = __ldg(g_srt + e), s1 = __ldg(g_srt + e + 1);
        float n0 = di * __ldg(g_dis + s0);
        float n1 = di * __ldg(g_dis + s1);
        float2 v0 = __half22float2(xh2[s0 * 32 + lane]);
        float2 v1 = __half22float2(xh2[s1 * 32 + lane]);
        acc.x += v0.x * n0 + v1.x * n1;
        acc.y += v0.y * n0 + v1.y * n1;
    }
    if (e < end) {
        int s0 = __ldg(g_srt + e);
        float n0 = di * __ldg(g_dis + s0);
        float2 v0 = __half22float2(xh2[s0 * 32 + lane]);
        acc.x += v0.x * n0; acc.y += v0.y * n0;
    }
    ((float2*)g_agg1)[node * 32 + lane] = acc;
}
// agg2[i] = h1h[i]*dis^2 + sum_e h1h[src]*nrm   (128 halves/row = 32 uint2; lane -> 4 floats)
__global__ __launch_bounds__(256) void k_gather2(int n) {
    int node = blockIdx.x * 8 + (threadIdx.x >> 5);
    int lane = threadIdx.x & 31;
    if (node >= n) return;
    float di = g_dis[node];
    const uint2* h2 = (const uint2*)g_h1h;
    uint2 us = h2[node * 32 + lane];
    float2 f0 = __half22float2(*(__half2*)&us.x);
    float2 f1 = __half22float2(*(__half2*)&us.y);
    float s2 = di * di;
    float4 acc = make_float4(f0.x * s2, f0.y * s2, f1.x * s2, f1.y * s2);
    int e = g_rp[node], end = g_rp[node + 1];
    for (; e + 1 < end; e += 2) {
        int s0 = __ldg(g_srt + e), s1 = __ldg(g_srt + e + 1);
        float n0 = di * __ldg(g_dis + s0);
        float n1 = di * __ldg(g_dis + s1);
        uint2 u0 = h2[s0 * 32 + lane];
        uint2 u1 = h2[s1 * 32 + lane];
        float2 a0 = __half22float2(*(__half2*)&u0.x);
        float2 a1 = __half22float2(*(__half2*)&u0.y);
        float2 b0 = __half22float2(*(__half2*)&u1.x);
        float2 b1 = __half22float2(*(__half2*)&u1.y);
        acc.x += a0.x * n0 + b0.x * n1;
        acc.y += a0.y * n0 + b0.y * n1;
        acc.z += a1.x * n0 + b1.x * n1;
        acc.w += a1.y * n0 + b1.y * n1;
    }
    if (e < end) {
        int s0 = __ldg(g_srt + e);
        float n0 = di * __ldg(g_dis + s0);
        uint2 u0 = h2[s0 * 32 + lane];
        float2 a0 = __half22float2(*(__half2*)&u0.x);
        float2 a1 = __half22float2(*(__half2*)&u0.y);
        acc.x += a0.x * n0; acc.y += a0.y * n0;
        acc.z += a1.x * n0; acc.w += a1.y * n0;
    }
    ((float4*)g_agg2)[node * 32 + lane] = acc;
}

// ---------------- fold prep (weights + bias in one kernel) ----------------
__global__ void k_foldw(const float* __restrict__ W2, const float* __restrict__ Wc1,
                        const float* __restrict__ b2, const float* __restrict__ bc1) {
    if (blockIdx.x == 128) {
        int n = threadIdx.x;
        int which = n >> 7, nn = n & 127;
        const float* wc = Wc1 + (which * 128) * 128 + nn;
        float acc = 0.f;
#pragma unroll 8
        for (int j = 0; j < 128; j++) acc = fmaf(b2[j], __ldg(wc + j * 128), acc);
        g_bf[n] = acc + (which ? 0.f : bc1[nn]);
        return;
    }
    int idx = blockIdx.x * 256 + threadIdx.x;
    int k = idx >> 8, n = idx & 255;
    int which = n >> 7, nn = n & 127;
    const float* w2row = W2 + k * 128;
    const float* wc = Wc1 + (which * 128) * 128 + nn;
    float acc = 0.f;
#pragma unroll 8
    for (int j = 0; j < 128; j++) acc = fmaf(__ldg(w2row + j), __ldg(wc + j * 128), acc);
    g_Wf[idx] = acc;
}

// ---------------- tf32 mma.sync GEMM ----------------
// OUTH: 0 = fp32 output, 1 = fp16 output
#define SA 68
template <bool RELU, int OUTH>
__global__ __launch_bounds__(256) void gemm_mma(
    const float* __restrict__ A, const float* __restrict__ W,
    const float* __restrict__ bias, void* __restrict__ Cv,
    int M, int K, int NC) {
    extern __shared__ uint32_t sm[];
    uint32_t* As = sm;              // 128*68
    uint32_t* Ws = sm + 128 * SA;   // 128*68
    int tid = threadIdx.x, wid = tid >> 5, lane = tid & 31;
    int row0 = blockIdx.x * 128, col0 = blockIdx.y * 128;
    int wm = (wid & 3) * 32, wn = (wid >> 2) * 64;
    int gid = lane >> 2, tig = lane & 3;

    float acc[2][8][4];
#pragma unroll
    for (int ma = 0; ma < 2; ma++)
#pragma unroll
        for (int na = 0; na < 8; na++)
#pragma unroll
            for (int q = 0; q < 4; q++) acc[ma][na][q] = 0.f;

    int lda4 = K >> 2;
    const float4* A4 = (const float4*)A;

    for (int kc = 0; kc < K; kc += 64) {
        for (int i = tid; i < 128 * 16; i += 256) {
            int r = i >> 4, kk = i & 15;
            float4 v = make_float4(0.f, 0.f, 0.f, 0.f);
            int gr = row0 + r;
            if (gr < M) v = A4[gr * lda4 + (kc >> 2) + kk];
            uint4 tv;
            tv.x = f2tf32(v.x); tv.y = f2tf32(v.y); tv.z = f2tf32(v.z); tv.w = f2tf32(v.w);
            *(uint4*)(As + r * SA + kk * 4) = tv;
        }
        for (int i = tid; i < 64 * 128; i += 256) {
            int k = i >> 7, n = i & 127;
            Ws[n * SA + k] = f2tf32(__ldg(W + (kc + k) * NC + col0 + n));
        }
        __syncthreads();

        const uint32_t* a0p = As + (wm + gid) * SA;
        const uint32_t* b0p = Ws + (wn + gid) * SA;
#pragma unroll
        for (int ks = 0; ks < 64; ks += 8) {
            uint32_t afr[2][4];
#pragma unroll
            for (int ma = 0; ma < 2; ma++) {
                const uint32_t* p = a0p + ma * 16 * SA + ks + tig;
                afr[ma][0] = p[0];
                afr[ma][1] = p[8 * SA];
                afr[ma][2] = p[4];
                afr[ma][3] = p[8 * SA + 4];
            }
#pragma unroll
            for (int na = 0; na < 8; na++) {
                const uint32_t* p = b0p + na * 8 * SA + ks + tig;
                uint32_t b0 = p[0], b1 = p[4];
                mma_tf32(acc[0][na], afr[0], b0, b1);
                mma_tf32(acc[1][na], afr[1], b0, b1);
            }
        }
        __syncthreads();
    }

#pragma unroll
    for (int ma = 0; ma < 2; ma++) {
        int r0 = row0 + wm + ma * 16 + gid;
#pragma unroll
        for (int na = 0; na < 8; na++) {
            int c = col0 + wn + na * 8 + 2 * tig;
            float bx = bias[c], by = bias[c + 1];
            float2 v0, v1;
            v0.x = acc[ma][na][0] + bx; v0.y = acc[ma][na][1] + by;
            v1.x = acc[ma][na][2] + bx; v1.y = acc[ma][na][3] + by;
            if (RELU) {
                v0.x = fmaxf(v0.x, 0.f); v0.y = fmaxf(v0.y, 0.f);
                v1.x = fmaxf(v1.x, 0.f); v1.y = fmaxf(v1.y, 0.f);
            }
            if (OUTH) {
                __half* C = (__half*)Cv;
                if (r0 < M)     *(__half2*)(C + (long)r0 * NC + c)       = __floats2half2_rn(v0.x, v0.y);
                if (r0 + 8 < M) *(__half2*)(C + (long)(r0 + 8) * NC + c) = __floats2half2_rn(v1.x, v1.y);
            } else {
                float* C = (float*)Cv;
                if (r0 < M)     *(float2*)(C + (long)r0 * NC + c)       = v0;
                if (r0 + 8 < M) *(float2*)(C + (long)(r0 + 8) * NC + c) = v1;
            }
        }
    }
}

// ---------------- query ----------------
__global__ void k_query(const int* __restrict__ eli, const float* __restrict__ Wc2,
                        const float* __restrict__ bc2, float* __restrict__ out, int Q) {
    int t = blockIdx.x * blockDim.x + threadIdx.x;
    int q = t >> 5, lane = t & 31;
    if (q >= Q) return;
    int s = __ldg(eli + q);
    int d = __ldg(eli + Q + q);
    float4 a = ((const float4*)g_AB)[s * 64 + lane];
    float4 b = ((const float4*)g_AB)[d * 64 + 32 + lane];
    float4 w = ((const float4*)Wc2)[lane];
    float ux = fmaxf(a.x + b.x, 0.f);
    float uy = fmaxf(a.y + b.y, 0.f);
    float uz = fmaxf(a.z + b.z, 0.f);
    float uw = fmaxf(a.w + b.w, 0.f);
    float sum = ux * w.x + uy * w.y + uz * w.z + uw * w.w;
#pragma unroll
    for (int o = 16; o > 0; o >>= 1) sum += __shfl_xor_sync(0xffffffffu, sum, o);
    if (lane == 0) out[q] = sum + bc2[0];
}

extern "C" void kernel_launch(void* const* d_in, const int* in_sizes, int n_in,
                              void* d_out, int out_size) {
    const float* x   = (const float*)d_in[0];
    const int*   ei  = (const int*)  d_in[1];
    const int*   eli = (const int*)  d_in[2];
    const float* W1  = (const float*)d_in[3];
    const float* b1  = (const float*)d_in[4];
    const float* W2  = (const float*)d_in[5];
    const float* b2  = (const float*)d_in[6];
    const float* Wc1 = (const float*)d_in[7];
    const float* bc1 = (const float*)d_in[8];
    const float* Wc2 = (const float*)d_in[9];
    const float* bc2 = (const float*)d_in[10];
    float* out = (float*)d_out;

    int N = in_sizes[0] / 64;
    int E = in_sizes[1] / 2;
    int Q = in_sizes[2] / 2;

    float *agg1, *ABp, *Wfp, *bfp, *agg2;
    __half* h1h;
    cudaGetSymbolAddress((void**)&agg1, g_agg1);
    cudaGetSymbolAddress((void**)&h1h,  g_h1h);
    cudaGetSymbolAddress((void**)&ABp,  g_AB);
    cudaGetSymbolAddress((void**)&Wfp,  g_Wf);
    cudaGetSymbolAddress((void**)&bfp,  g_bf);
    cudaGetSymbolAddress((void**)&agg2, g_agg2);

    const int GSMEM = 2 * 128 * SA * 4;   // 69632 B
    cudaFuncSetAttribute(gemm_mma<true, 1>,
                         cudaFuncAttributeMaxDynamicSharedMemorySize, GSMEM);
    cudaFuncSetAttribute(gemm_mma<false, 0>,
                         cudaFuncAttributeMaxDynamicSharedMemorySize, GSMEM);

    const int B = 256;
    int gblk = (N + 127) / 128;
    int nwarp_blk = (N + 7) / 8;
    int scan_g = (N + SCAN_B - 1) / SCAN_B;

    // CSR build + x convert (independent kernels first for overlap)
    k_zero    <<<(N + B - 1) / B, B>>>(N);
    k_count   <<<(E + B - 1) / B, B>>>(ei, E);
    k_xcvt    <<<(N * 16 + B - 1) / B, B>>>(x, N * 16);
    k_scan_blk<<<scan_g, SCAN_B>>>(N);
    k_scan_add<<<scan_g, SCAN_B>>>(N, scan_g);
    k_permute <<<(E + B - 1) / B, B>>>(ei, E);
    // weight fold prep (weights + bias in one kernel)
    k_foldw   <<<129, 256>>>(W2, Wc1, b2, bc1);
    // conv1
    k_gather1 <<<nwarp_blk, B>>>(N);
    gemm_mma<true, 1> <<<dim3(gblk, 1), 256, GSMEM>>>(agg1, W1, b1, h1h, N, 64, 128);
    // conv2 (+ folded classifier layer 1)
    k_gather2 <<<nwarp_blk, B>>>(N);
    gemm_mma<false, 0><<<dim3(gblk, 2), 256, GSMEM>>>(agg2, Wfp, bfp, ABp, N, 128, 256);
    // query
    k_query   <<<((long)Q * 32 + B - 1) / B, B>>>(eli, Wc2, bc2, out, Q);
}

// round 12
// speedup vs baseline: 1.5461x; 1.0236x over previous
#include <cuda_runtime.h>
#include <cuda_fp16.h>
#include <cstdint>

#define N_NODES 50000
#define E_MAX   850000
#define SCAN_B  1024

// ---------------- scratch (allocation-free: __device__ globals) ----------------
__device__ __align__(128) int    g_cntr[N_NODES];
__device__ __align__(128) int    g_cntc[N_NODES];
__device__ __align__(128) int    g_rp  [N_NODES + 1];
__device__ __align__(128) int    g_fill[N_NODES];
__device__ __align__(128) int    g_bsum[64];
__device__ __align__(128) int    g_srt [E_MAX];
__device__ __align__(128) float  g_dis [N_NODES];
__device__ __align__(128) __half g_xh  [N_NODES * 64];    // fp16 copy of x
__device__ __align__(128) float  g_agg1[N_NODES * 64];
__device__ __align__(128) __half g_h1h [N_NODES * 128];   // fp16 h1
__device__ __align__(128) float  g_agg2[N_NODES * 128];
__device__ __align__(128) __half g_ABh [N_NODES * 256];   // fp16 [A | B] per node
__device__ __align__(128) float  g_Wf  [128 * 256];       // W2 @ [Wc1_top | Wc1_bot]
__device__ __align__(128) float  g_bf  [256];             // [b2@Wc1_top + bc1 | b2@Wc1_bot]

// ---------------- helpers ----------------
__device__ __forceinline__ uint32_t f2tf32(float f) {
    uint32_t r; asm("cvt.rna.tf32.f32 %0, %1;" : "=r"(r) : "f"(f)); return r;
}
__device__ __forceinline__ void mma_tf32(float* d, const uint32_t* a, uint32_t b0, uint32_t b1) {
    asm volatile(
        "mma.sync.aligned.m16n8k8.row.col.f32.tf32.tf32.f32 "
        "{%0,%1,%2,%3}, {%4,%5,%6,%7}, {%8,%9}, {%0,%1,%2,%3};"
        : "+f"(d[0]), "+f"(d[1]), "+f"(d[2]), "+f"(d[3])
        : "r"(a[0]), "r"(a[1]), "r"(a[2]), "r"(a[3]), "r"(b0), "r"(b1));
}

// ---------------- CSR build ----------------
__global__ void k_zero(int n) {
    int i = blockIdx.x * blockDim.x + threadIdx.x;
    if (i < n) { g_cntr[i] = 0; g_cntc[i] = 0; }
}
__global__ void k_count(const int* __restrict__ ei, int E) {
    int e = blockIdx.x * blockDim.x + threadIdx.x;
    if (e >= E) return;
    atomicAdd(&g_cntr[__ldg(ei + e)], 1);
    atomicAdd(&g_cntc[__ldg(ei + E + e)], 1);
}
// phase 1: per-block exclusive scan of cntc; also dis = rsqrt(1+cntr)
__global__ __launch_bounds__(SCAN_B) void k_scan_blk(int n) {
    __shared__ int wsum[32];
    int tid = threadIdx.x, lane = tid & 31, wid = tid >> 5;
    int i = blockIdx.x * SCAN_B + tid;
    if (i < n) g_dis[i] = rsqrtf(1.0f + (float)g_cntr[i]);
    int v = (i < n) ? g_cntc[i] : 0;
    int s = v;
#pragma unroll
    for (int o = 1; o < 32; o <<= 1) {
        int t = __shfl_up_sync(0xffffffffu, s, o);
        if (lane >= o) s += t;
    }
    if (lane == 31) wsum[wid] = s;
    __syncthreads();
    if (wid == 0) {
        int ws = wsum[lane];
#pragma unroll
        for (int o = 1; o < 32; o <<= 1) {
            int t = __shfl_up_sync(0xffffffffu, ws, o);
            if (lane >= o) ws += t;
        }
        wsum[lane] = ws;
    }
    __syncthreads();
    int incl = s + (wid ? wsum[wid - 1] : 0);
    if (i < n) g_rp[i] = incl - v;
    if (tid == SCAN_B - 1) g_bsum[blockIdx.x] = incl;
}
// phase 2+3 merged: each block reduces its own offset from g_bsum, then adds.
__global__ __launch_bounds__(SCAN_B) void k_scan_add(int n, int nblk) {
    __shared__ int red[2];
    int b = blockIdx.x, tid = threadIdx.x;
    if (tid < 64) {
        int v = (tid < b) ? g_bsum[tid] : 0;
#pragma unroll
        for (int o = 16; o > 0; o >>= 1) v += __shfl_down_sync(0xffffffffu, v, o);
        if ((tid & 31) == 0) red[tid >> 5] = v;
    }
    __syncthreads();
    int off = red[0] + red[1];
    int i = b * SCAN_B + tid;
    if (i < n) {
        int v = g_rp[i] + off;
        g_rp[i] = v;
        g_fill[i] = v;
    }
    if (b == nblk - 1 && tid == 0) g_rp[n] = off + g_bsum[b];
}
__global__ void k_permute(const int* __restrict__ ei, int E) {
    int e = blockIdx.x * blockDim.x + threadIdx.x;
    if (e >= E) return;
    int r = __ldg(ei + e);
    int c = __ldg(ei + E + e);
    int pos = atomicAdd(&g_fill[c], 1);
    g_srt[pos] = r;
}

// ---------------- x -> fp16 convert ----------------
__global__ void k_xcvt(const float* __restrict__ x, int n16) {   // n16 = N*16 float4s
    int i = blockIdx.x * blockDim.x + threadIdx.x;
    if (i >= n16) return;
    float4 v = ((const float4*)x)[i];
    __half2 a = __floats2half2_rn(v.x, v.y);
    __half2 b = __floats2half2_rn(v.z, v.w);
    uint2 u;
    u.x = *(uint32_t*)&a;
    u.y = *(uint32_t*)&b;
    ((uint2*)g_xh)[i] = u;
}

// ---------------- gather convs (warp per node; lane-parallel index loads) ----------------
// agg1[i] = xh[i]*dis^2 + sum_e xh[src]*nrm
__global__ __launch_bounds__(256) void k_gather1(int n) {
    int node = blockIdx.x * 8 + (threadIdx.x >> 5);
    int lane = threadIdx.x & 31;
    if (node >= n) return;
    float di = g_dis[node];
    const __half2* xh2 = (const __half2*)g_xh;
    float2 acc = __half22float2(xh2[node * 32 + lane]);
    float s2 = di * di;
    acc.x *= s2; acc.y *= s2;
    int e = g_rp[node], end = g_rp[node + 1];
    while (e < end) {
        int cnt = end - e;
        if (cnt > 32) cnt = 32;
        int idx = 0; float dn = 0.f;
        if (lane < cnt) {
            idx = __ldg(g_srt + e + lane);
            dn  = di * __ldg(g_dis + idx);
        }
#pragma unroll 4
        for (int j = 0; j < cnt; j++) {
            int   s  = __shfl_sync(0xffffffffu, idx, j);
            float nm = __shfl_sync(0xffffffffu, dn, j);
            float2 v = __half22float2(xh2[s * 32 + lane]);
            acc.x += v.x * nm;
            acc.y += v.y * nm;
        }
        e += cnt;
    }
    ((float2*)g_agg1)[node * 32 + lane] = acc;
}
// agg2[i] = h1h[i]*dis^2 + sum_e h1h[src]*nrm
__global__ __launch_bounds__(256) void k_gather2(int n) {
    int node = blockIdx.x * 8 + (threadIdx.x >> 5);
    int lane = threadIdx.x & 31;
    if (node >= n) return;
    float di = g_dis[node];
    const uint2* h2 = (const uint2*)g_h1h;
    uint2 us = h2[node * 32 + lane];
    float2 f0 = __half22float2(*(__half2*)&us.x);
    float2 f1 = __half22float2(*(__half2*)&us.y);
    float s2 = di * di;
    float4 acc = make_float4(f0.x * s2, f0.y * s2, f1.x * s2, f1.y * s2);
    int e = g_rp[node], end = g_rp[node + 1];
    while (e < end) {
        int cnt = end - e;
        if (cnt > 32) cnt = 32;
        int idx = 0; float dn = 0.f;
        if (lane < cnt) {
            idx = __ldg(g_srt + e + lane);
            dn  = di * __ldg(g_dis + idx);
        }
#pragma unroll 4
        for (int j = 0; j < cnt; j++) {
            int   s  = __shfl_sync(0xffffffffu, idx, j);
            float nm = __shfl_sync(0xffffffffu, dn, j);
            uint2 u0 = h2[s * 32 + lane];
            float2 a0 = __half22float2(*(__half2*)&u0.x);
            float2 a1 = __half22float2(*(__half2*)&u0.y);
            acc.x += a0.x * nm;
            acc.y += a0.y * nm;
            acc.z += a1.x * nm;
            acc.w += a1.y * nm;
        }
        e += cnt;
    }
    ((float4*)g_agg2)[node * 32 + lane] = acc;
}

// ---------------- fold prep (weights + bias in one kernel) ----------------
__global__ void k_foldw(const float* __restrict__ W2, const float* __restrict__ Wc1,
                        const float* __restrict__ b2, const float* __restrict__ bc1) {
    if (blockIdx.x == 128) {
        int n = threadIdx.x;
        int which = n >> 7, nn = n & 127;
        const float* wc = Wc1 + (which * 128) * 128 + nn;
        float acc = 0.f;
#pragma unroll 8
        for (int j = 0; j < 128; j++) acc = fmaf(b2[j], __ldg(wc + j * 128), acc);
        g_bf[n] = acc + (which ? 0.f : bc1[nn]);
        return;
    }
    int idx = blockIdx.x * 256 + threadIdx.x;
    int k = idx >> 8, n = idx & 255;
    int which = n >> 7, nn = n & 127;
    const float* w2row = W2 + k * 128;
    const float* wc = Wc1 + (which * 128) * 128 + nn;
    float acc = 0.f;
#pragma unroll 8
    for (int j = 0; j < 128; j++) acc = fmaf(__ldg(w2row + j), __ldg(wc + j * 128), acc);
    g_Wf[idx] = acc;
}

// ---------------- tf32 mma.sync GEMM ----------------
// OUTH: 0 = fp32 output, 1 = fp16 output
#define SA 68
template <bool RELU, int OUTH>
__global__ __launch_bounds__(256) void gemm_mma(
    const float* __restrict__ A, const float* __restrict__ W,
    const float* __restrict__ bias, void* __restrict__ Cv,
    int M, int K, int NC) {
    extern __shared__ uint32_t sm[];
    uint32_t* As = sm;              // 128*68
    uint32_t* Ws = sm + 128 * SA;   // 128*68
    int tid = threadIdx.x, wid = tid >> 5, lane = tid & 31;
    int row0 = blockIdx.x * 128, col0 = blockIdx.y * 128;
    int wm = (wid & 3) * 32, wn = (wid >> 2) * 64;
    int gid = lane >> 2, tig = lane & 3;

    float acc[2][8][4];
#pragma unroll
    for (int ma = 0; ma < 2; ma++)
#pragma unroll
        for (int na = 0; na < 8; na++)
#pragma unroll
            for (int q = 0; q < 4; q++) acc[ma][na][q] = 0.f;

    int lda4 = K >> 2;
    const float4* A4 = (const float4*)A;

    for (int kc = 0; kc < K; kc += 64) {
        for (int i = tid; i < 128 * 16; i += 256) {
            int r = i >> 4, kk = i & 15;
            float4 v = make_float4(0.f, 0.f, 0.f, 0.f);
            int gr = row0 + r;
            if (gr < M) v = A4[gr * lda4 + (kc >> 2) + kk];
            uint4 tv;
            tv.x = f2tf32(v.x); tv.y = f2tf32(v.y); tv.z = f2tf32(v.z); tv.w = f2tf32(v.w);
            *(uint4*)(As + r * SA + kk * 4) = tv;
        }
        for (int i = tid; i < 64 * 128; i += 256) {
            int k = i >> 7, n = i & 127;
            Ws[n * SA + k] = f2tf32(__ldg(W + (kc + k) * NC + col0 + n));
        }
        __syncthreads();

        const uint32_t* a0p = As + (wm + gid) * SA;
        const uint32_t* b0p = Ws + (wn + gid) * SA;
#pragma unroll
        for (int ks = 0; ks < 64; ks += 8) {
            uint32_t afr[2][4];
#pragma unroll
            for (int ma = 0; ma < 2; ma++) {
                const uint32_t* p = a0p + ma * 16 * SA + ks + tig;
                afr[ma][0] = p[0];
                afr[ma][1] = p[8 * SA];
                afr[ma][2] = p[4];
                afr[ma][3] = p[8 * SA + 4];
            }
#pragma unroll
            for (int na = 0; na < 8; na++) {
                const uint32_t* p = b0p + na * 8 * SA + ks + tig;
                uint32_t b0 = p[0], b1 = p[4];
                mma_tf32(acc[0][na], afr[0], b0, b1);
                mma_tf32(acc[1][na], afr[1], b0, b1);
            }
        }
        __syncthreads();
    }

#pragma unroll
    for (int ma = 0; ma < 2; ma++) {
        int r0 = row0 + wm + ma * 16 + gid;
#pragma unroll
        for (int na = 0; na < 8; na++) {
            int c = col0 + wn + na * 8 + 2 * tig;
            float bx = bias[c], by = bias[c + 1];
            float2 v0, v1;
            v0.x = acc[ma][na][0] + bx; v0.y = acc[ma][na][1] + by;
            v1.x = acc[ma][na][2] + bx; v1.y = acc[ma][na][3] + by;
            if (RELU) {
                v0.x = fmaxf(v0.x, 0.f); v0.y = fmaxf(v0.y, 0.f);
                v1.x = fmaxf(v1.x, 0.f); v1.y = fmaxf(v1.y, 0.f);
            }
            if (OUTH) {
                __half* C = (__half*)Cv;
                if (r0 < M)     *(__half2*)(C + (long)r0 * NC + c)       = __floats2half2_rn(v0.x, v0.y);
                if (r0 + 8 < M) *(__half2*)(C + (long)(r0 + 8) * NC + c) = __floats2half2_rn(v1.x, v1.y);
            } else {
                float* C = (float*)Cv;
                if (r0 < M)     *(float2*)(C + (long)r0 * NC + c)       = v0;
                if (r0 + 8 < M) *(float2*)(C + (long)(r0 + 8) * NC + c) = v1;
            }
        }
    }
}

// ---------------- query (fp16 AB reads) ----------------
__global__ void k_query(const int* __restrict__ eli, const float* __restrict__ Wc2,
                        const float* __restrict__ bc2, float* __restrict__ out, int Q) {
    int t = blockIdx.x * blockDim.x + threadIdx.x;
    int q = t >> 5, lane = t & 31;
    if (q >= Q) return;
    int s = __ldg(eli + q);
    int d = __ldg(eli + Q + q);
    const uint2* AB2 = (const uint2*)g_ABh;    // 4 halves per lane
    uint2 ua = AB2[s * 64 + lane];
    uint2 ub = AB2[d * 64 + 32 + lane];
    float2 a0 = __half22float2(*(__half2*)&ua.x);
    float2 a1 = __half22float2(*(__half2*)&ua.y);
    float2 b0 = __half22float2(*(__half2*)&ub.x);
    float2 b1 = __half22float2(*(__half2*)&ub.y);
    float4 w = ((const float4*)Wc2)[lane];
    float ux = fmaxf(a0.x + b0.x, 0.f);
    float uy = fmaxf(a0.y + b0.y, 0.f);
    float uz = fmaxf(a1.x + b1.x, 0.f);
    float uw = fmaxf(a1.y + b1.y, 0.f);
    float sum = ux * w.x + uy * w.y + uz * w.z + uw * w.w;
#pragma unroll
    for (int o = 16; o > 0; o >>= 1) sum += __shfl_xor_sync(0xffffffffu, sum, o);
    if (lane == 0) out[q] = sum + bc2[0];
}

extern "C" void kernel_launch(void* const* d_in, const int* in_sizes, int n_in,
                              void* d_out, int out_size) {
    const float* x   = (const float*)d_in[0];
    const int*   ei  = (const int*)  d_in[1];
    const int*   eli = (const int*)  d_in[2];
    const float* W1  = (const float*)d_in[3];
    const float* b1  = (const float*)d_in[4];
    const float* W2  = (const float*)d_in[5];
    const float* b2  = (const float*)d_in[6];
    const float* Wc1 = (const float*)d_in[7];
    const float* bc1 = (const float*)d_in[8];
    const float* Wc2 = (const float*)d_in[9];
    const float* bc2 = (const float*)d_in[10];
    float* out = (float*)d_out;

    int N = in_sizes[0] / 64;
    int E = in_sizes[1] / 2;
    int Q = in_sizes[2] / 2;

    float *agg1, *Wfp, *bfp, *agg2;
    __half *h1h, *ABh;
    cudaGetSymbolAddress((void**)&agg1, g_agg1);
    cudaGetSymbolAddress((void**)&h1h,  g_h1h);
    cudaGetSymbolAddress((void**)&ABh,  g_ABh);
    cudaGetSymbolAddress((void**)&Wfp,  g_Wf);
    cudaGetSymbolAddress((void**)&bfp,  g_bf);
    cudaGetSymbolAddress((void**)&agg2, g_agg2);

    const int GSMEM = 2 * 128 * SA * 4;   // 69632 B
    cudaFuncSetAttribute(gemm_mma<true, 1>,
                         cudaFuncAttributeMaxDynamicSharedMemorySize, GSMEM);
    cudaFuncSetAttribute(gemm_mma<false, 1>,
                         cudaFuncAttributeMaxDynamicSharedMemorySize, GSMEM);

    const int B = 256;
    int gblk = (N + 127) / 128;
    int nwarp_blk = (N + 7) / 8;
    int scan_g = (N + SCAN_B - 1) / SCAN_B;

    // CSR build + x convert
    k_zero    <<<(N + B - 1) / B, B>>>(N);
    k_count   <<<(E + B - 1) / B, B>>>(ei, E);
    k_xcvt    <<<(N * 16 + B - 1) / B, B>>>(x, N * 16);
    k_scan_blk<<<scan_g, SCAN_B>>>(N);
    k_scan_add<<<scan_g, SCAN_B>>>(N, scan_g);
    k_permute <<<(E + B - 1) / B, B>>>(ei, E);
    // weight fold prep
    k_foldw   <<<129, 256>>>(W2, Wc1, b2, bc1);
    // conv1
    k_gather1 <<<nwarp_blk, B>>>(N);
    gemm_mma<true, 1> <<<dim3(gblk, 1), 256, GSMEM>>>(agg1, W1, b1, h1h, N, 64, 128);
    // conv2 (+ folded classifier layer 1)
    k_gather2 <<<nwarp_blk, B>>>(N);
    gemm_mma<false, 1><<<dim3(gblk, 2), 256, GSMEM>>>(agg2, Wfp, bfp, ABh, N, 128, 256);
    // query
    k_query   <<<((long)Q * 32 + B - 1) / B, B>>>(eli, Wc2, bc2, out, Q);
}